// round 6
// baseline (speedup 1.0000x reference)
#include <cuda_runtime.h>
#include <cuda_bf16.h>
#include <math.h>
#include <stdint.h>

// ----------------------------------------------------------------------------
// Problem constants (fixed shapes)
// ----------------------------------------------------------------------------
#define BB   4
#define TT   1024
#define SS   4096
#define DD   1024
#define HH   16
#define HD   64

__constant__ int c_stride[HH] = {1,2,4,8, 1,2,4,8, 1,2,4,8, 1,2,4,8};
__constant__ int c_hmap[HH] = {0,4,8,12, 1,5,9,13, 2,6,10,14, 3,7,11,15};

// Scratch (device globals are the allowed scratch mechanism)
__device__ float g_Q[(size_t)BB * TT * DD];
__device__ float g_K[(size_t)BB * SS * DD];
__device__ float g_V[(size_t)BB * SS * DD];
__device__ float g_attn[(size_t)BB * TT * DD];
__device__ float g_decT[(size_t)BB * TT * DD];
__device__ float g_encT[(size_t)BB * SS * DD];
__device__ float g_Wq[(size_t)DD * DD];
__device__ float g_Wk[(size_t)DD * DD];
__device__ float g_Wv[(size_t)DD * DD];
__device__ float g_Wo[(size_t)DD * DD];

// ----------------------------------------------------------------------------
// Helpers (sm_100 baseline features only)
// ----------------------------------------------------------------------------
__device__ __forceinline__ uint32_t smem_u32(const void* p) {
    uint32_t a;
    asm("{ .reg .u64 t; cvta.to.shared.u64 t, %1; cvt.u32.u64 %0, t; }"
        : "=r"(a) : "l"(p));
    return a;
}
__device__ __forceinline__ uint32_t f2tf32(float x) {
    uint32_t o;
    asm("cvt.rna.tf32.f32 %0, %1;" : "=r"(o) : "f"(x));
    return o;
}
__device__ __forceinline__ void ldmatrix_x4(uint32_t* f, uint32_t addr) {
    asm volatile("ldmatrix.sync.aligned.m8n8.x4.shared.b16 {%0,%1,%2,%3}, [%4];"
                 : "=r"(f[0]), "=r"(f[1]), "=r"(f[2]), "=r"(f[3]) : "r"(addr));
}
__device__ __forceinline__ void mma_tf32(float* c, const uint32_t* a,
                                         uint32_t b0, uint32_t b1) {
    asm volatile(
        "mma.sync.aligned.m16n8k8.row.col.f32.tf32.tf32.f32 "
        "{%0,%1,%2,%3}, {%4,%5,%6,%7}, {%8,%9}, {%0,%1,%2,%3};"
        : "+f"(c[0]), "+f"(c[1]), "+f"(c[2]), "+f"(c[3])
        : "r"(a[0]), "r"(a[1]), "r"(a[2]), "r"(a[3]), "r"(b0), "r"(b1));
}
__device__ __forceinline__ void cp16(uint32_t saddr, const void* g) {
    asm volatile("cp.async.cg.shared.global [%0], [%1], 16;"
                 :: "r"(saddr), "l"(g) : "memory");
}
#define CP_COMMIT() asm volatile("cp.async.commit_group;" ::: "memory")
#define CP_WAIT(n)  asm volatile("cp.async.wait_group %0;" :: "n"(n) : "memory")

// ----------------------------------------------------------------------------
// Pre-round pass: dst[i] = tf32_rna(src[i])
// ----------------------------------------------------------------------------
__global__ void round_tf32_kernel(const float* __restrict__ src,
                                  float* __restrict__ dst, int n4)
{
    int i = blockIdx.x * blockDim.x + threadIdx.x;
    if (i < n4) {
        float4 v = ((const float4*)src)[i];
        uint4 u;
        u.x = f2tf32(v.x); u.y = f2tf32(v.y);
        u.z = f2tf32(v.z); u.w = f2tf32(v.w);
        ((uint4*)dst)[i] = u;
    }
}

// ----------------------------------------------------------------------------
// Tensor-core tf32 GEMM v3:  CTA tile 128x256, warp tile 64x64, BK=32.
// 8 warps 2(m)x4(n). 3-stage cp.async. Inputs pre-rounded tf32.
// ----------------------------------------------------------------------------
#define GM_BK 32
#define GM_ATILE (128 * 128)            // 16KB
#define GM_BTILE (256 * 128)            // 32KB
#define GM_STAGE (GM_ATILE + GM_BTILE)  // 48KB
#define GM_SMEM  (3 * GM_STAGE)         // 144KB

static __device__ __forceinline__ uint32_t tile_off(int row, int seg) {
    return (uint32_t)(row * 128 + ((seg ^ (row & 7)) << 4));
}

template<bool ROUND>
__device__ __forceinline__ void gemm_core(const float* __restrict__ A,
                                          const float* __restrict__ W,
                                          const float* __restrict__ bias,
                                          float* __restrict__ C,
                                          int mt, int nt)
{
    extern __shared__ char sm_raw[];
    const uint32_t smBase = smem_u32(sm_raw);
    const int K = DD, N = DD;

    const int tid  = threadIdx.x;
    const int wid  = tid >> 5;
    const int lane = tid & 31;

    const int row0 = mt * 128;
    const int col0 = nt * 256;

    const int warp_m0 = (wid >> 2) * 64;
    const int warp_n0 = (wid & 3) * 64;
    const int rrow = (lane & 7) + (((lane >> 3) & 1) << 3);
    const int sadd = lane >> 4;

    const float* Ap = A + (size_t)row0 * K;
    const float* Wp = W + (size_t)col0 * K;

    const int l_row = tid >> 3;      // 0..31
    const int l_seg = tid & 7;

    auto issue = [&](int c, int st) {
        const uint32_t sa = smBase + st * GM_STAGE;
        const float* ga = Ap + c * GM_BK + l_seg * 4;
        const float* gb = Wp + c * GM_BK + l_seg * 4;
#pragma unroll
        for (int it = 0; it < 4; ++it) {
            const int row = l_row + it * 32;
            cp16(sa + tile_off(row, l_seg), ga + (size_t)row * K);
        }
#pragma unroll
        for (int it = 0; it < 8; ++it) {
            const int row = l_row + it * 32;
            cp16(sa + GM_ATILE + tile_off(row, l_seg), gb + (size_t)row * K);
        }
        CP_COMMIT();
    };

    float acc[4][8][4];
#pragma unroll
    for (int i = 0; i < 4; ++i)
#pragma unroll
        for (int j = 0; j < 8; ++j)
#pragma unroll
            for (int q = 0; q < 4; ++q) acc[i][j][q] = 0.f;

    const int NCH = K / GM_BK;   // 32
    issue(0, 0);
    issue(1, 1);

    for (int c = 0; c < NCH; ++c) {
        const int s = c % 3;
        CP_WAIT(1);
        __syncthreads();
        if (c + 2 < NCH) issue(c + 2, (c + 2) % 3);

        const uint32_t aBase = smBase + s * GM_STAGE;
        const uint32_t bBase = aBase + GM_ATILE;
#pragma unroll
        for (int k = 0; k < 4; ++k) {
            const int seg = k * 2 + sadd;
            uint32_t af[4][4], bf[4][4];
#pragma unroll
            for (int i = 0; i < 4; ++i)
                ldmatrix_x4(af[i], aBase + tile_off(warp_m0 + 16 * i + rrow, seg));
#pragma unroll
            for (int j = 0; j < 4; ++j)
                ldmatrix_x4(bf[j], bBase + tile_off(warp_n0 + 16 * j + rrow, seg));
#pragma unroll
            for (int i = 0; i < 4; ++i)
#pragma unroll
                for (int j = 0; j < 4; ++j) {
                    mma_tf32(acc[i][2 * j],     af[i], bf[j][0], bf[j][2]);
                    mma_tf32(acc[i][2 * j + 1], af[i], bf[j][1], bf[j][3]);
                }
        }
        __syncthreads();
    }

    // epilogue
    {
        const int g = lane >> 2;
        const int t = lane & 3;
#pragma unroll
        for (int i = 0; i < 4; ++i) {
            const int r = row0 + warp_m0 + 16 * i + g;
#pragma unroll
            for (int jb = 0; jb < 8; ++jb) {
                const int cc = col0 + warp_n0 + 8 * jb + 2 * t;
                const float bx = __ldg(&bias[cc]);
                const float by = __ldg(&bias[cc + 1]);
                float o0 = acc[i][jb][0] + bx, o1 = acc[i][jb][1] + by;
                float o2 = acc[i][jb][2] + bx, o3 = acc[i][jb][3] + by;
                if (ROUND) {
                    o0 = __uint_as_float(f2tf32(o0));
                    o1 = __uint_as_float(f2tf32(o1));
                    o2 = __uint_as_float(f2tf32(o2));
                    o3 = __uint_as_float(f2tf32(o3));
                }
                *(float2*)&C[(size_t)r * N + cc]       = make_float2(o0, o1);
                *(float2*)&C[(size_t)(r + 8) * N + cc] = make_float2(o2, o3);
            }
        }
    }
}

// Fused Q/K/V projections: 1152 CTAs (128 Q + 512 K + 512 V); 4 n-tiles each
__global__ __launch_bounds__(256, 1)
void gemm_qkv_kernel(const float* __restrict__ decT, const float* __restrict__ encT,
                     const float* __restrict__ Wq, const float* __restrict__ Wk,
                     const float* __restrict__ Wv,
                     const float* __restrict__ bq, const float* __restrict__ bk,
                     const float* __restrict__ bv,
                     float* __restrict__ Qo, float* __restrict__ Ko,
                     float* __restrict__ Vo)
{
    int id = blockIdx.x;
    const float *A, *W, *bias;
    float* C;
    if (id < 128)       { A = decT; W = Wq; bias = bq; C = Qo; }
    else if (id < 640)  { A = encT; W = Wk; bias = bk; C = Ko; id -= 128; }
    else                { A = encT; W = Wv; bias = bv; C = Vo; id -= 640; }
    gemm_core<true>(A, W, bias, C, id >> 2, id & 3);
}

__global__ __launch_bounds__(256, 1)
void gemm_o_kernel(const float* __restrict__ A, const float* __restrict__ W,
                   const float* __restrict__ bias, float* __restrict__ C)
{
    gemm_core<false>(A, W, bias, C, blockIdx.x >> 2, blockIdx.x & 3);
}

// ----------------------------------------------------------------------------
// Tensor-core flash attention v3: double-buffered K (cp.async) and V.
// CTA: 64 queries x one (b,h); 128 threads (4 warps).
// Smem: Qs 16K | Ks[2] 32K | Vt[2] 32K | Ps 16K = 96KB. 2 CTAs/SM.
// ----------------------------------------------------------------------------
#define FA_SMEM_BYTES (96 * 1024)

static __device__ __forceinline__ uint32_t toff2(int row, int seg) {
    return (uint32_t)(row * 256 + ((seg ^ (row & 7)) << 4));
}

__global__ __launch_bounds__(128, 2)
void flash_tc_kernel(const float* __restrict__ Q,
                     const float* __restrict__ K,
                     const float* __restrict__ V,
                     float* __restrict__ O)
{
    extern __shared__ char sm_raw[];
    const uint32_t QsB  = smem_u32(sm_raw);
    const uint32_t KsB0 = QsB + 16384;          // Ks[0], Ks[1] at +16K
    const uint32_t VtB0 = QsB + 49152;          // Vt[0], Vt[1] at +16K
    const uint32_t PsB  = QsB + 81920;

    const int tid  = threadIdx.x;
    const int wid  = tid >> 5;
    const int lane = tid & 31;

    const int y  = blockIdx.y;
    const int b  = y & 3;
    const int h  = c_hmap[y >> 2];
    const int stride = c_stride[h];
    const int t0 = blockIdx.x * 64;

    const int rrow = (lane & 7) + (((lane >> 3) & 1) << 3);
    const int sadd = lane >> 4;
    const int g    = lane >> 2;
    const int t    = lane & 3;
    const int w16  = wid * 16;

    const float C1 = 0.125f * 1.4426950408889634f;

    const int k_row = tid >> 4;   // K/Q loader: 0..7 (+8 per pass)
    const int k_seg = tid & 15;
    const int s_loc = tid & 63;   // V loader: key index
    const int dh    = (tid >> 6) * 32;

    const float* Kb = K + ((size_t)b * SS) * DD + h * HD;
    const float* Vb = V + ((size_t)b * SS) * DD + h * HD;

    auto kissue = [&](int tile, int s) {
        const uint32_t dstB = KsB0 + s * 16384;
#pragma unroll
        for (int it = 0; it < 8; ++it) {
            const int r = k_row + it * 8;
            const int srow = (tile * 64 + r) * stride;
            cp16(dstB + toff2(r, k_seg), Kb + (size_t)srow * DD + k_seg * 4);
        }
        CP_COMMIT();
    };

    // ---- prologue: Q + K0 via cp.async (one group) ----
    {
        const float* qb = Q + ((size_t)(b * TT + t0)) * DD + h * HD;
#pragma unroll
        for (int it = 0; it < 8; ++it) {
            const int r = k_row + it * 8;
            cp16(QsB + toff2(r, k_seg), qb + (size_t)r * DD + k_seg * 4);
        }
    }
    kissue(0, 0);

    float m0 = -INFINITY, m1 = -INFINITY, l0 = 0.f, l1 = 0.f;
    float acc_o[8][4];
#pragma unroll
    for (int jb = 0; jb < 8; ++jb)
#pragma unroll
        for (int q = 0; q < 4; ++q) acc_o[jb][q] = 0.f;

    const int nTiles = SS / (stride * 64);

    for (int tile = 0; tile < nTiles; ++tile) {
        const int s = tile & 1;
        const uint32_t Ks = KsB0 + s * 16384;
        const uint32_t Vt = VtB0 + s * 16384;

        // ---- V(tile) LDG + scatter STS into Vt[s] ----
        {
            const int srow = (tile * 64 + s_loc) * stride;
            const float* vb = Vb + (size_t)srow * DD + dh;
#pragma unroll
            for (int p = 0; p < 8; ++p) {
                float4 v = *(const float4*)(vb + p * 4);
                const float vv[4] = {v.x, v.y, v.z, v.w};
#pragma unroll
                for (int e = 0; e < 4; ++e) {
                    const int d = dh + p * 4 + e;
                    *(float*)(sm_raw + (Vt - QsB) + d * 256 +
                              (((s_loc >> 2) ^ (d & 7)) << 4) + (s_loc & 3) * 4)
                        = vv[e];
                }
            }
        }
        CP_WAIT(0);        // K(tile) [and Q on iter 0] arrived
        __syncthreads();   // + V stores visible

        // ---- S = Q @ K^T ----
        float s_[8][4];
#pragma unroll
        for (int jb = 0; jb < 8; ++jb)
#pragma unroll
            for (int q = 0; q < 4; ++q) s_[jb][q] = 0.f;

#pragma unroll
        for (int k = 0; k < 8; ++k) {
            const int seg = k * 2 + sadd;
            uint32_t af[4];
            ldmatrix_x4(af, QsB + toff2(w16 + rrow, seg));
#pragma unroll
            for (int j = 0; j < 4; ++j) {
                uint32_t bf[4];
                ldmatrix_x4(bf, Ks + toff2(16 * j + rrow, seg));
                mma_tf32(s_[2 * j],     af, bf[0], bf[2]);
                mma_tf32(s_[2 * j + 1], af, bf[1], bf[3]);
            }
        }
#pragma unroll
        for (int jb = 0; jb < 8; ++jb)
#pragma unroll
            for (int q = 0; q < 4; ++q) s_[jb][q] *= C1;

        // ---- online softmax ----
        float tm0 = -INFINITY, tm1 = -INFINITY;
#pragma unroll
        for (int jb = 0; jb < 8; ++jb) {
            tm0 = fmaxf(tm0, fmaxf(s_[jb][0], s_[jb][1]));
            tm1 = fmaxf(tm1, fmaxf(s_[jb][2], s_[jb][3]));
        }
#pragma unroll
        for (int msk = 1; msk < 4; msk <<= 1) {
            tm0 = fmaxf(tm0, __shfl_xor_sync(0xffffffffu, tm0, msk));
            tm1 = fmaxf(tm1, __shfl_xor_sync(0xffffffffu, tm1, msk));
        }
        const float mn0 = fmaxf(m0, tm0);
        const float mn1 = fmaxf(m1, tm1);
        const float cr0 = exp2f(m0 - mn0);
        const float cr1 = exp2f(m1 - mn1);
        m0 = mn0; m1 = mn1;

        float sum0 = 0.f, sum1 = 0.f;
#pragma unroll
        for (int jb = 0; jb < 8; ++jb) {
            const float p0 = exp2f(s_[jb][0] - mn0);
            const float p1 = exp2f(s_[jb][1] - mn0);
            const float p2 = exp2f(s_[jb][2] - mn1);
            const float p3 = exp2f(s_[jb][3] - mn1);
            sum0 += p0 + p1;
            sum1 += p2 + p3;
            const int c0  = jb * 8 + 2 * t;
            const int seg = c0 >> 2;
            const int ofs = (c0 & 3) * 4;
            const int rA  = w16 + g;
            const int rB  = rA + 8;
            *(uint2*)(sm_raw + (PsB - QsB) + rA * 256 +
                      ((seg ^ (rA & 7)) << 4) + ofs) = make_uint2(f2tf32(p0), f2tf32(p1));
            *(uint2*)(sm_raw + (PsB - QsB) + rB * 256 +
                      ((seg ^ (rB & 7)) << 4) + ofs) = make_uint2(f2tf32(p2), f2tf32(p3));
        }
#pragma unroll
        for (int msk = 1; msk < 4; msk <<= 1) {
            sum0 += __shfl_xor_sync(0xffffffffu, sum0, msk);
            sum1 += __shfl_xor_sync(0xffffffffu, sum1, msk);
        }
        l0 = l0 * cr0 + sum0;
        l1 = l1 * cr1 + sum1;
#pragma unroll
        for (int jb = 0; jb < 8; ++jb) {
            acc_o[jb][0] *= cr0; acc_o[jb][1] *= cr0;
            acc_o[jb][2] *= cr1; acc_o[jb][3] *= cr1;
        }
        __syncwarp();

        // ---- prefetch K(tile+1) into Ks[s^1] (safe: all warps passed top barrier) ----
        if (tile + 1 < nTiles) kissue(tile + 1, s ^ 1);

        // ---- O += P @ V ----
#pragma unroll
        for (int k = 0; k < 8; ++k) {
            const int seg = k * 2 + sadd;
            uint32_t af[4];
            ldmatrix_x4(af, PsB + toff2(w16 + rrow, seg));
#pragma unroll
            for (int j = 0; j < 4; ++j) {
                uint32_t bf[4];
                ldmatrix_x4(bf, Vt + toff2(16 * j + rrow, seg));
                mma_tf32(acc_o[2 * j],     af, bf[0], bf[2]);
                mma_tf32(acc_o[2 * j + 1], af, bf[1], bf[3]);
            }
        }
    }

    // ---- epilogue ----
    {
        const float inv0 = 1.0f / l0;
        const float inv1 = 1.0f / l1;
        const int r0 = t0 + w16 + g;
        const int r1 = r0 + 8;
#pragma unroll
        for (int jb = 0; jb < 8; ++jb) {
            const int d = jb * 8 + 2 * t;
            uint2 u0 = make_uint2(f2tf32(acc_o[jb][0] * inv0),
                                  f2tf32(acc_o[jb][1] * inv0));
            uint2 u1 = make_uint2(f2tf32(acc_o[jb][2] * inv1),
                                  f2tf32(acc_o[jb][3] * inv1));
            *(uint2*)&O[((size_t)(b * TT + r0)) * DD + h * HD + d] = u0;
            *(uint2*)&O[((size_t)(b * TT + r1)) * DD + h * HD + d] = u1;
        }
    }
}

// ----------------------------------------------------------------------------
// Launch
// ----------------------------------------------------------------------------
extern "C" void kernel_launch(void* const* d_in, const int* in_sizes, int n_in,
                              void* d_out, int out_size)
{
    const float* dec = (const float*)d_in[0];
    const float* enc = (const float*)d_in[1];
    const float* Wq  = (const float*)d_in[2];
    const float* bq  = (const float*)d_in[3];
    const float* Wk  = (const float*)d_in[4];
    const float* bk  = (const float*)d_in[5];
    const float* Wv  = (const float*)d_in[6];
    const float* bv  = (const float*)d_in[7];
    const float* Wo  = (const float*)d_in[8];
    const float* bo  = (const float*)d_in[9];
    float* out = (float*)d_out;

    float *gQ, *gK, *gV, *gA, *gDec, *gEnc, *gWq, *gWk, *gWv, *gWo;
    cudaGetSymbolAddress((void**)&gQ,   g_Q);
    cudaGetSymbolAddress((void**)&gK,   g_K);
    cudaGetSymbolAddress((void**)&gV,   g_V);
    cudaGetSymbolAddress((void**)&gA,   g_attn);
    cudaGetSymbolAddress((void**)&gDec, g_decT);
    cudaGetSymbolAddress((void**)&gEnc, g_encT);
    cudaGetSymbolAddress((void**)&gWq,  g_Wq);
    cudaGetSymbolAddress((void**)&gWk,  g_Wk);
    cudaGetSymbolAddress((void**)&gWv,  g_Wv);
    cudaGetSymbolAddress((void**)&gWo,  g_Wo);

    cudaFuncSetAttribute(gemm_qkv_kernel,
                         cudaFuncAttributeMaxDynamicSharedMemorySize, GM_SMEM);
    cudaFuncSetAttribute(gemm_o_kernel,
                         cudaFuncAttributeMaxDynamicSharedMemorySize, GM_SMEM);
    cudaFuncSetAttribute(flash_tc_kernel,
                         cudaFuncAttributeMaxDynamicSharedMemorySize, FA_SMEM_BYTES);

    // ---- pre-round inputs to tf32 ----
    {
        const int nDec = BB * TT * DD / 4, nEnc = BB * SS * DD / 4, nW = DD * DD / 4;
        round_tf32_kernel<<<(nDec + 255) / 256, 256>>>(dec, gDec, nDec);
        round_tf32_kernel<<<(nEnc + 255) / 256, 256>>>(enc, gEnc, nEnc);
        round_tf32_kernel<<<(nW   + 255) / 256, 256>>>(Wq,  gWq,  nW);
        round_tf32_kernel<<<(nW   + 255) / 256, 256>>>(Wk,  gWk,  nW);
        round_tf32_kernel<<<(nW   + 255) / 256, 256>>>(Wv,  gWv,  nW);
        round_tf32_kernel<<<(nW   + 255) / 256, 256>>>(Wo,  gWo,  nW);
    }

    // ---- fused Q/K/V projections ----
    gemm_qkv_kernel<<<1152, 256, GM_SMEM>>>(gDec, gEnc, gWq, gWk, gWv,
                                            bq, bk, bv, gQ, gK, gV);

    // ---- attention ----
    {
        dim3 grid(TT / 64, BB * HH);
        flash_tc_kernel<<<grid, 128, FA_SMEM_BYTES>>>(gQ, gK, gV, gA);
    }

    // ---- output projection ----
    gemm_o_kernel<<<128, 256, GM_SMEM>>>(gA, gWo, bo, out);
}

// round 7
// speedup vs baseline: 2.1770x; 2.1770x over previous
#include <cuda_runtime.h>
#include <cuda_fp16.h>
#include <math.h>
#include <stdint.h>

// ----------------------------------------------------------------------------
// Problem constants (fixed shapes)
// ----------------------------------------------------------------------------
#define BB   4
#define TT   1024
#define SS   4096
#define DD   1024
#define HH   16
#define HD   64

__constant__ int c_stride[HH] = {1,2,4,8, 1,2,4,8, 1,2,4,8, 1,2,4,8};
__constant__ int c_hmap[HH] = {0,4,8,12, 1,5,9,13, 2,6,10,14, 3,7,11,15};

// Scratch (device globals are the allowed scratch mechanism) — fp16 everywhere
__device__ __half g_Qh[(size_t)BB * TT * DD];
__device__ __half g_Kh[(size_t)BB * SS * DD];
__device__ __half g_Vh[(size_t)BB * SS * DD];
__device__ __half g_attnH[(size_t)BB * TT * DD];
__device__ __half g_decH[(size_t)BB * TT * DD];
__device__ __half g_encH[(size_t)BB * SS * DD];
__device__ __half g_WqH[(size_t)DD * DD];
__device__ __half g_WkH[(size_t)DD * DD];
__device__ __half g_WvH[(size_t)DD * DD];
__device__ __half g_WoH[(size_t)DD * DD];

// ----------------------------------------------------------------------------
// Helpers (sm_100 baseline features only)
// ----------------------------------------------------------------------------
__device__ __forceinline__ uint32_t smem_u32(const void* p) {
    uint32_t a;
    asm("{ .reg .u64 t; cvta.to.shared.u64 t, %1; cvt.u32.u64 %0, t; }"
        : "=r"(a) : "l"(p));
    return a;
}
__device__ __forceinline__ uint32_t h2u(float a, float b) {
    __half2 h = __floats2half2_rn(a, b);
    return *reinterpret_cast<uint32_t*>(&h);
}
__device__ __forceinline__ void ldmatrix_x4(uint32_t* f, uint32_t addr) {
    asm volatile("ldmatrix.sync.aligned.m8n8.x4.shared.b16 {%0,%1,%2,%3}, [%4];"
                 : "=r"(f[0]), "=r"(f[1]), "=r"(f[2]), "=r"(f[3]) : "r"(addr));
}
__device__ __forceinline__ void ldmatrix_x4_trans(uint32_t* f, uint32_t addr) {
    asm volatile("ldmatrix.sync.aligned.m8n8.x4.trans.shared.b16 {%0,%1,%2,%3}, [%4];"
                 : "=r"(f[0]), "=r"(f[1]), "=r"(f[2]), "=r"(f[3]) : "r"(addr));
}
// D(f32) = A(f16) @ B(f16) + D ;  m16n8k16
__device__ __forceinline__ void mma_h(float* c, const uint32_t* a,
                                      uint32_t b0, uint32_t b1) {
    asm volatile(
        "mma.sync.aligned.m16n8k16.row.col.f32.f16.f16.f32 "
        "{%0,%1,%2,%3}, {%4,%5,%6,%7}, {%8,%9}, {%0,%1,%2,%3};"
        : "+f"(c[0]), "+f"(c[1]), "+f"(c[2]), "+f"(c[3])
        : "r"(a[0]), "r"(a[1]), "r"(a[2]), "r"(a[3]), "r"(b0), "r"(b1));
}
__device__ __forceinline__ void cp16(uint32_t saddr, const void* g) {
    asm volatile("cp.async.cg.shared.global [%0], [%1], 16;"
                 :: "r"(saddr), "l"(g) : "memory");
}
#define CP_COMMIT() asm volatile("cp.async.commit_group;" ::: "memory")
#define CP_WAIT(n)  asm volatile("cp.async.wait_group %0;" :: "n"(n) : "memory")

// ----------------------------------------------------------------------------
// Pre-convert pass: fp32 -> fp16
// ----------------------------------------------------------------------------
__global__ void to_half_kernel(const float* __restrict__ src,
                               __half* __restrict__ dst, int n4)
{
    int i = blockIdx.x * blockDim.x + threadIdx.x;
    if (i < n4) {
        float4 v = ((const float4*)src)[i];
        uint2 u;
        u.x = h2u(v.x, v.y);
        u.y = h2u(v.z, v.w);
        ((uint2*)dst)[i] = u;
    }
}

// ----------------------------------------------------------------------------
// fp16 tensor-core GEMM:  C[M,N] = A[M,K] @ W[N,K]^T + bias[N]
// CTA tile 128x128, BK=64 halfs (128B rows), 8 warps 2(m)x4(n) warp tile 64x32.
// 3-stage cp.async. 2 CTAs/SM.
// ----------------------------------------------------------------------------
#define GM_BK 64
#define GM_TILE  (128 * 128)            // 16KB (128 rows x 128B)
#define GM_STAGE (2 * GM_TILE)          // 32KB
#define GM_SMEM  (3 * GM_STAGE)         // 96KB

static __device__ __forceinline__ uint32_t tile_off(int row, int seg) {
    return (uint32_t)(row * 128 + ((seg ^ (row & 7)) << 4));
}

template<bool HALF_OUT>
__device__ __forceinline__ void gemm_core_h(const __half* __restrict__ A,
                                            const __half* __restrict__ W,
                                            const float* __restrict__ bias,
                                            void* __restrict__ Cout,
                                            int mt, int nt)
{
    extern __shared__ char sm_raw[];
    const uint32_t smBase = smem_u32(sm_raw);
    const int K = DD, N = DD;

    const int tid  = threadIdx.x;
    const int wid  = tid >> 5;
    const int lane = tid & 31;

    const int row0 = mt * 128;
    const int col0 = nt * 128;

    const int warp_m0 = (wid >> 2) * 64;
    const int warp_n0 = (wid & 3) * 32;
    const int rrow = (lane & 7) + (((lane >> 3) & 1) << 3);
    const int sadd = lane >> 4;

    const __half* Ap = A + (size_t)row0 * K;
    const __half* Wp = W + (size_t)col0 * K;

    const int l_seg = tid & 7;

    auto issue = [&](int c, int st) {
        const uint32_t sa = smBase + st * GM_STAGE;
        const __half* ga = Ap + c * GM_BK + l_seg * 8;
        const __half* gb = Wp + c * GM_BK + l_seg * 8;
#pragma unroll
        for (int it = 0; it < 4; ++it) {
            const int row = (tid + it * 256) >> 3;
            cp16(sa + tile_off(row, l_seg), ga + (size_t)row * K);
        }
#pragma unroll
        for (int it = 0; it < 4; ++it) {
            const int row = (tid + it * 256) >> 3;
            cp16(sa + GM_TILE + tile_off(row, l_seg), gb + (size_t)row * K);
        }
        CP_COMMIT();
    };

    float acc[4][4][4];
#pragma unroll
    for (int i = 0; i < 4; ++i)
#pragma unroll
        for (int j = 0; j < 4; ++j)
#pragma unroll
            for (int q = 0; q < 4; ++q) acc[i][j][q] = 0.f;

    const int NCH = K / GM_BK;   // 16
    issue(0, 0);
    issue(1, 1);

    for (int c = 0; c < NCH; ++c) {
        const int s = c % 3;
        CP_WAIT(1);
        __syncthreads();
        if (c + 2 < NCH) issue(c + 2, (c + 2) % 3);

        const uint32_t aBase = smBase + s * GM_STAGE;
        const uint32_t bBase = aBase + GM_TILE;
#pragma unroll
        for (int k = 0; k < 4; ++k) {          // 4 x k16
            const int seg = k * 2 + sadd;
            uint32_t af[4][4], bf[2][4];
#pragma unroll
            for (int i = 0; i < 4; ++i)
                ldmatrix_x4(af[i], aBase + tile_off(warp_m0 + 16 * i + rrow, seg));
#pragma unroll
            for (int j = 0; j < 2; ++j)
                ldmatrix_x4(bf[j], bBase + tile_off(warp_n0 + 16 * j + rrow, seg));
#pragma unroll
            for (int i = 0; i < 4; ++i)
#pragma unroll
                for (int j = 0; j < 2; ++j) {
                    mma_h(acc[i][2 * j],     af[i], bf[j][0], bf[j][2]);
                    mma_h(acc[i][2 * j + 1], af[i], bf[j][1], bf[j][3]);
                }
        }
        __syncthreads();
    }

    // epilogue
    {
        const int g = lane >> 2;
        const int t = lane & 3;
#pragma unroll
        for (int i = 0; i < 4; ++i) {
            const int r = row0 + warp_m0 + 16 * i + g;
#pragma unroll
            for (int jb = 0; jb < 4; ++jb) {
                const int cc = col0 + warp_n0 + 8 * jb + 2 * t;
                const float bx = __ldg(&bias[cc]);
                const float by = __ldg(&bias[cc + 1]);
                const float o0 = acc[i][jb][0] + bx, o1 = acc[i][jb][1] + by;
                const float o2 = acc[i][jb][2] + bx, o3 = acc[i][jb][3] + by;
                if (HALF_OUT) {
                    __half* C = (__half*)Cout;
                    *(uint32_t*)&C[(size_t)r * N + cc]       = h2u(o0, o1);
                    *(uint32_t*)&C[(size_t)(r + 8) * N + cc] = h2u(o2, o3);
                } else {
                    float* C = (float*)Cout;
                    *(float2*)&C[(size_t)r * N + cc]       = make_float2(o0, o1);
                    *(float2*)&C[(size_t)(r + 8) * N + cc] = make_float2(o2, o3);
                }
            }
        }
    }
}

// Fused Q/K/V projections: 2304 CTAs (256 Q + 1024 K + 1024 V)
__global__ __launch_bounds__(256, 2)
void gemm_qkv_kernel(const __half* __restrict__ decH, const __half* __restrict__ encH,
                     const __half* __restrict__ Wq, const __half* __restrict__ Wk,
                     const __half* __restrict__ Wv,
                     const float* __restrict__ bq, const float* __restrict__ bk,
                     const float* __restrict__ bv,
                     __half* __restrict__ Qo, __half* __restrict__ Ko,
                     __half* __restrict__ Vo)
{
    int id = blockIdx.x;
    const __half *A, *W;
    const float* bias;
    __half* C;
    if (id < 256)        { A = decH; W = Wq; bias = bq; C = Qo; }
    else if (id < 1280)  { A = encH; W = Wk; bias = bk; C = Ko; id -= 256; }
    else                 { A = encH; W = Wv; bias = bv; C = Vo; id -= 1280; }
    gemm_core_h<true>(A, W, bias, C, id >> 3, id & 7);
}

__global__ __launch_bounds__(256, 2)
void gemm_o_kernel(const __half* __restrict__ A, const __half* __restrict__ W,
                   const float* __restrict__ bias, float* __restrict__ C)
{
    gemm_core_h<false>(A, W, bias, C, blockIdx.x >> 3, blockIdx.x & 7);
}

// ----------------------------------------------------------------------------
// fp16 tensor-core flash attention v4.
// CTA: 64 queries x one (b,h); 128 threads (4 warps), warp w -> rows [16w,16w+16).
// K/V tiles of 64 keys, double buffered via cp.async. P stays in registers
// (S-accum fragment == A-operand fragment after half2 pack). V used via
// ldmatrix.trans (no explicit transpose).
// Smem: Qs 8K | Ks[2] 16K | Vs[2] 16K = 40KB -> 4 CTAs/SM.
// ----------------------------------------------------------------------------
#define FA_SMEM_BYTES (40 * 1024)

__global__ __launch_bounds__(128, 4)
void flash_h_kernel(const __half* __restrict__ Q,
                    const __half* __restrict__ K,
                    const __half* __restrict__ V,
                    __half* __restrict__ O)
{
    extern __shared__ char sm_raw[];
    const uint32_t QsB  = smem_u32(sm_raw);
    const uint32_t KsB0 = QsB + 8192;    // Ks[0] @8K, Ks[1] @16K
    const uint32_t VsB0 = QsB + 24576;   // Vs[0] @24K, Vs[1] @32K

    const int tid  = threadIdx.x;
    const int wid  = tid >> 5;
    const int lane = tid & 31;

    const int y  = blockIdx.y;
    const int b  = y & 3;
    const int h  = c_hmap[y >> 2];
    const int stride = c_stride[h];
    const int t0 = blockIdx.x * 64;

    const int rrow = (lane & 7) + (((lane >> 3) & 1) << 3);
    const int sadd = lane >> 4;
    const int g    = lane >> 2;
    const int t    = lane & 3;
    const int w16  = wid * 16;

    const float C1 = 0.125f * 1.4426950408889634f;  // scale * log2(e)

    const int l_seg = tid & 7;     // loader: 64 rows x 8 segs = 512 cp16 / 128 thr

    const __half* Kb = K + ((size_t)b * SS) * DD + h * HD;
    const __half* Vb = V + ((size_t)b * SS) * DD + h * HD;

    auto kv_issue = [&](int tile, int s) {
        const uint32_t kd = KsB0 + s * 8192;
        const uint32_t vd = VsB0 + s * 8192;
#pragma unroll
        for (int it = 0; it < 4; ++it) {
            const int row = (tid + it * 128) >> 3;
            const int srow = (tile * 64 + row) * stride;
            cp16(kd + tile_off(row, l_seg), Kb + (size_t)srow * DD + l_seg * 8);
        }
#pragma unroll
        for (int it = 0; it < 4; ++it) {
            const int row = (tid + it * 128) >> 3;
            const int srow = (tile * 64 + row) * stride;
            cp16(vd + tile_off(row, l_seg), Vb + (size_t)srow * DD + l_seg * 8);
        }
        CP_COMMIT();
    };

    // ---- prologue: Q + K0 + V0 as one group ----
    {
        const __half* qb = Q + ((size_t)(b * TT + t0)) * DD + h * HD;
#pragma unroll
        for (int it = 0; it < 4; ++it) {
            const int row = (tid + it * 128) >> 3;
            cp16(QsB + tile_off(row, l_seg), qb + (size_t)row * DD + l_seg * 8);
        }
    }
    kv_issue(0, 0);

    uint32_t qf[4][4];
    float m0 = -INFINITY, m1 = -INFINITY, l0 = 0.f, l1 = 0.f;
    float acc_o[8][4];
#pragma unroll
    for (int jb = 0; jb < 8; ++jb)
#pragma unroll
        for (int q = 0; q < 4; ++q) acc_o[jb][q] = 0.f;

    const int nTiles = SS / (stride * 64);

    for (int tile = 0; tile < nTiles; ++tile) {
        const int s = tile & 1;
        const uint32_t Ks = KsB0 + s * 8192;
        const uint32_t Vs = VsB0 + s * 8192;

        CP_WAIT(0);        // K/V(tile) (and Q on tile 0) arrived
        __syncthreads();   // all warps done with buffer s^1

        if (tile == 0) {   // hoist Q fragments into registers (reused all tiles)
#pragma unroll
            for (int k = 0; k < 4; ++k)
                ldmatrix_x4(qf[k], QsB + tile_off(w16 + rrow, k * 2 + sadd));
        }
        if (tile + 1 < nTiles) kv_issue(tile + 1, s ^ 1);

        // ---- S = Q @ K^T  (warp: 16 q-rows x 64 keys) ----
        float s_[8][4];
#pragma unroll
        for (int jb = 0; jb < 8; ++jb)
#pragma unroll
            for (int q = 0; q < 4; ++q) s_[jb][q] = 0.f;

#pragma unroll
        for (int k = 0; k < 4; ++k) {
            const int seg = k * 2 + sadd;
#pragma unroll
            for (int j = 0; j < 4; ++j) {
                uint32_t bf[4];
                ldmatrix_x4(bf, Ks + tile_off(16 * j + rrow, seg));
                mma_h(s_[2 * j],     qf[k], bf[0], bf[2]);
                mma_h(s_[2 * j + 1], qf[k], bf[1], bf[3]);
            }
        }
#pragma unroll
        for (int jb = 0; jb < 8; ++jb)
#pragma unroll
            for (int q = 0; q < 4; ++q) s_[jb][q] *= C1;

        // ---- online softmax (rows g, g+8; 4 lanes share a row) ----
        float tm0 = -INFINITY, tm1 = -INFINITY;
#pragma unroll
        for (int jb = 0; jb < 8; ++jb) {
            tm0 = fmaxf(tm0, fmaxf(s_[jb][0], s_[jb][1]));
            tm1 = fmaxf(tm1, fmaxf(s_[jb][2], s_[jb][3]));
        }
#pragma unroll
        for (int msk = 1; msk < 4; msk <<= 1) {
            tm0 = fmaxf(tm0, __shfl_xor_sync(0xffffffffu, tm0, msk));
            tm1 = fmaxf(tm1, __shfl_xor_sync(0xffffffffu, tm1, msk));
        }
        const float mn0 = fmaxf(m0, tm0);
        const float mn1 = fmaxf(m1, tm1);
        const float cr0 = exp2f(m0 - mn0);
        const float cr1 = exp2f(m1 - mn1);
        m0 = mn0; m1 = mn1;

        float sum0 = 0.f, sum1 = 0.f;
#pragma unroll
        for (int jb = 0; jb < 8; ++jb) {
            s_[jb][0] = exp2f(s_[jb][0] - mn0);
            s_[jb][1] = exp2f(s_[jb][1] - mn0);
            s_[jb][2] = exp2f(s_[jb][2] - mn1);
            s_[jb][3] = exp2f(s_[jb][3] - mn1);
            sum0 += s_[jb][0] + s_[jb][1];
            sum1 += s_[jb][2] + s_[jb][3];
        }
#pragma unroll
        for (int msk = 1; msk < 4; msk <<= 1) {
            sum0 += __shfl_xor_sync(0xffffffffu, sum0, msk);
            sum1 += __shfl_xor_sync(0xffffffffu, sum1, msk);
        }
        l0 = l0 * cr0 + sum0;
        l1 = l1 * cr1 + sum1;
#pragma unroll
        for (int jb = 0; jb < 8; ++jb) {
            acc_o[jb][0] *= cr0; acc_o[jb][1] *= cr0;
            acc_o[jb][2] *= cr1; acc_o[jb][3] *= cr1;
        }

        // ---- O += P @ V   (P packed from registers; V via ldmatrix.trans) ----
#pragma unroll
        for (int kk = 0; kk < 4; ++kk) {       // key blocks of 16
            uint32_t ap[4];
            ap[0] = h2u(s_[2 * kk][0],     s_[2 * kk][1]);
            ap[1] = h2u(s_[2 * kk][2],     s_[2 * kk][3]);
            ap[2] = h2u(s_[2 * kk + 1][0], s_[2 * kk + 1][1]);
            ap[3] = h2u(s_[2 * kk + 1][2], s_[2 * kk + 1][3]);
#pragma unroll
            for (int jj = 0; jj < 4; ++jj) {   // d blocks of 16
                uint32_t bf[4];
                ldmatrix_x4_trans(bf, Vs + tile_off(16 * kk + rrow, 2 * jj + sadd));
                mma_h(acc_o[2 * jj],     ap, bf[0], bf[1]);
                mma_h(acc_o[2 * jj + 1], ap, bf[2], bf[3]);
            }
        }
    }

    // ---- epilogue: normalize, write half ----
    {
        const float inv0 = 1.0f / l0;
        const float inv1 = 1.0f / l1;
        const int r0 = t0 + w16 + g;
        const int r1 = r0 + 8;
#pragma unroll
        for (int jb = 0; jb < 8; ++jb) {
            const int d = jb * 8 + 2 * t;
            *(uint32_t*)&O[((size_t)(b * TT + r0)) * DD + h * HD + d] =
                h2u(acc_o[jb][0] * inv0, acc_o[jb][1] * inv0);
            *(uint32_t*)&O[((size_t)(b * TT + r1)) * DD + h * HD + d] =
                h2u(acc_o[jb][2] * inv1, acc_o[jb][3] * inv1);
        }
    }
}

// ----------------------------------------------------------------------------
// Launch
// ----------------------------------------------------------------------------
extern "C" void kernel_launch(void* const* d_in, const int* in_sizes, int n_in,
                              void* d_out, int out_size)
{
    const float* dec = (const float*)d_in[0];
    const float* enc = (const float*)d_in[1];
    const float* Wq  = (const float*)d_in[2];
    const float* bq  = (const float*)d_in[3];
    const float* Wk  = (const float*)d_in[4];
    const float* bk  = (const float*)d_in[5];
    const float* Wv  = (const float*)d_in[6];
    const float* bv  = (const float*)d_in[7];
    const float* Wo  = (const float*)d_in[8];
    const float* bo  = (const float*)d_in[9];
    float* out = (float*)d_out;

    __half *gQ, *gK, *gV, *gA, *gDec, *gEnc, *gWq, *gWk, *gWv, *gWo;
    cudaGetSymbolAddress((void**)&gQ,   g_Qh);
    cudaGetSymbolAddress((void**)&gK,   g_Kh);
    cudaGetSymbolAddress((void**)&gV,   g_Vh);
    cudaGetSymbolAddress((void**)&gA,   g_attnH);
    cudaGetSymbolAddress((void**)&gDec, g_decH);
    cudaGetSymbolAddress((void**)&gEnc, g_encH);
    cudaGetSymbolAddress((void**)&gWq,  g_WqH);
    cudaGetSymbolAddress((void**)&gWk,  g_WkH);
    cudaGetSymbolAddress((void**)&gWv,  g_WvH);
    cudaGetSymbolAddress((void**)&gWo,  g_WoH);

    cudaFuncSetAttribute(gemm_qkv_kernel,
                         cudaFuncAttributeMaxDynamicSharedMemorySize, GM_SMEM);
    cudaFuncSetAttribute(gemm_o_kernel,
                         cudaFuncAttributeMaxDynamicSharedMemorySize, GM_SMEM);
    cudaFuncSetAttribute(flash_h_kernel,
                         cudaFuncAttributeMaxDynamicSharedMemorySize, FA_SMEM_BYTES);

    // ---- convert inputs to fp16 ----
    {
        const int nDec = BB * TT * DD / 4, nEnc = BB * SS * DD / 4, nW = DD * DD / 4;
        to_half_kernel<<<(nDec + 255) / 256, 256>>>(dec, gDec, nDec);
        to_half_kernel<<<(nEnc + 255) / 256, 256>>>(enc, gEnc, nEnc);
        to_half_kernel<<<(nW   + 255) / 256, 256>>>(Wq,  gWq,  nW);
        to_half_kernel<<<(nW   + 255) / 256, 256>>>(Wk,  gWk,  nW);
        to_half_kernel<<<(nW   + 255) / 256, 256>>>(Wv,  gWv,  nW);
        to_half_kernel<<<(nW   + 255) / 256, 256>>>(Wo,  gWo,  nW);
    }

    // ---- fused Q/K/V projections ----
    gemm_qkv_kernel<<<2304, 256, GM_SMEM>>>(gDec, gEnc, gWq, gWk, gWv,
                                            bq, bk, bv, gQ, gK, gV);

    // ---- attention ----
    {
        dim3 grid(TT / 64, BB * HH);
        flash_h_kernel<<<grid, 128, FA_SMEM_BYTES>>>(gQ, gK, gV, gA);
    }

    // ---- output projection ----
    gemm_o_kernel<<<256, 256, GM_SMEM>>>(gA, gWo, bo, out);
}

// round 8
// speedup vs baseline: 2.1868x; 1.0045x over previous
#include <cuda_runtime.h>
#include <cuda_fp16.h>
#include <math.h>
#include <stdint.h>

// ----------------------------------------------------------------------------
// Problem constants (fixed shapes)
// ----------------------------------------------------------------------------
#define BB   4
#define TT   1024
#define SS   4096
#define DD   1024
#define HH   16
#define HD   64

__constant__ int c_stride[HH] = {1,2,4,8, 1,2,4,8, 1,2,4,8, 1,2,4,8};
__constant__ int c_hmap[HH] = {0,4,8,12, 1,5,9,13, 2,6,10,14, 3,7,11,15};

// Scratch (device globals are the allowed scratch mechanism) — fp16 everywhere
__device__ __half g_Qh[(size_t)BB * TT * DD];
__device__ __half g_Kh[(size_t)BB * SS * DD];
__device__ __half g_Vh[(size_t)BB * SS * DD];
__device__ __half g_attnH[(size_t)BB * TT * DD];
__device__ __half g_decH[(size_t)BB * TT * DD];
__device__ __half g_encH[(size_t)BB * SS * DD];
__device__ __half g_WqH[(size_t)DD * DD];
__device__ __half g_WkH[(size_t)DD * DD];
__device__ __half g_WvH[(size_t)DD * DD];
__device__ __half g_WoH[(size_t)DD * DD];

// ----------------------------------------------------------------------------
// Helpers (sm_100 baseline features only)
// ----------------------------------------------------------------------------
__device__ __forceinline__ uint32_t smem_u32(const void* p) {
    uint32_t a;
    asm("{ .reg .u64 t; cvta.to.shared.u64 t, %1; cvt.u32.u64 %0, t; }"
        : "=r"(a) : "l"(p));
    return a;
}
__device__ __forceinline__ uint32_t h2u(float a, float b) {
    __half2 h = __floats2half2_rn(a, b);
    return *reinterpret_cast<uint32_t*>(&h);
}
__device__ __forceinline__ void ldmatrix_x4(uint32_t* f, uint32_t addr) {
    asm volatile("ldmatrix.sync.aligned.m8n8.x4.shared.b16 {%0,%1,%2,%3}, [%4];"
                 : "=r"(f[0]), "=r"(f[1]), "=r"(f[2]), "=r"(f[3]) : "r"(addr));
}
__device__ __forceinline__ void ldmatrix_x4_trans(uint32_t* f, uint32_t addr) {
    asm volatile("ldmatrix.sync.aligned.m8n8.x4.trans.shared.b16 {%0,%1,%2,%3}, [%4];"
                 : "=r"(f[0]), "=r"(f[1]), "=r"(f[2]), "=r"(f[3]) : "r"(addr));
}
// D(f32) = A(f16) @ B(f16) + D ;  m16n8k16
__device__ __forceinline__ void mma_h(float* c, const uint32_t* a,
                                      uint32_t b0, uint32_t b1) {
    asm volatile(
        "mma.sync.aligned.m16n8k16.row.col.f32.f16.f16.f32 "
        "{%0,%1,%2,%3}, {%4,%5,%6,%7}, {%8,%9}, {%0,%1,%2,%3};"
        : "+f"(c[0]), "+f"(c[1]), "+f"(c[2]), "+f"(c[3])
        : "r"(a[0]), "r"(a[1]), "r"(a[2]), "r"(a[3]), "r"(b0), "r"(b1));
}
__device__ __forceinline__ void cp16(uint32_t saddr, const void* g) {
    asm volatile("cp.async.cg.shared.global [%0], [%1], 16;"
                 :: "r"(saddr), "l"(g) : "memory");
}
#define CP_COMMIT() asm volatile("cp.async.commit_group;" ::: "memory")
#define CP_WAIT(n)  asm volatile("cp.async.wait_group %0;" :: "n"(n) : "memory")

// ----------------------------------------------------------------------------
// Fused pre-convert pass: fp32 -> fp16 for all six inputs in one launch
// ----------------------------------------------------------------------------
#define N4_ENC (BB * SS * DD / 4)
#define N4_DEC (BB * TT * DD / 4)
#define N4_W   (DD * DD / 4)

__global__ void to_half_all_kernel(const float* __restrict__ dec,
                                   const float* __restrict__ enc,
                                   const float* __restrict__ Wq,
                                   const float* __restrict__ Wk,
                                   const float* __restrict__ Wv,
                                   const float* __restrict__ Wo,
                                   __half* __restrict__ dDec,
                                   __half* __restrict__ dEnc,
                                   __half* __restrict__ dWq,
                                   __half* __restrict__ dWk,
                                   __half* __restrict__ dWv,
                                   __half* __restrict__ dWo)
{
    int i = blockIdx.x * blockDim.x + threadIdx.x;
    const float* src;
    __half* dst;
    int off;
    if (i < N4_ENC) {
        src = enc; dst = dEnc; off = i;
    } else if (i < N4_ENC + N4_DEC) {
        src = dec; dst = dDec; off = i - N4_ENC;
    } else {
        int j = i - N4_ENC - N4_DEC;
        int w = j / N4_W;
        off = j - w * N4_W;
        src = (w == 0) ? Wq : (w == 1) ? Wk : (w == 2) ? Wv : Wo;
        dst = (w == 0) ? dWq : (w == 1) ? dWk : (w == 2) ? dWv : dWo;
    }
    float4 v = ((const float4*)src)[off];
    uint2 u;
    u.x = h2u(v.x, v.y);
    u.y = h2u(v.z, v.w);
    ((uint2*)dst)[off] = u;
}

// ----------------------------------------------------------------------------
// fp16 tensor-core GEMM:  C[M,N] = A[M,K] @ W[N,K]^T + bias[N]
// CTA tile 128x256, warp tile 64x64 (8 warps 2m x 4n), BK=64 halfs.
// 3-stage cp.async (144KB smem), 1 CTA/SM, ~190 regs.
// ----------------------------------------------------------------------------
#define GM_BK 64
#define GM_ATILE (128 * 128)              // 16KB (128 rows x 128B)
#define GM_BTILE (256 * 128)              // 32KB (256 rows x 128B)
#define GM_STAGE (GM_ATILE + GM_BTILE)    // 48KB
#define GM_SMEM  (3 * GM_STAGE)           // 144KB

static __device__ __forceinline__ uint32_t tile_off(int row, int seg) {
    return (uint32_t)(row * 128 + ((seg ^ (row & 7)) << 4));
}

template<bool HALF_OUT>
__device__ __forceinline__ void gemm_core_h(const __half* __restrict__ A,
                                            const __half* __restrict__ W,
                                            const float* __restrict__ bias,
                                            void* __restrict__ Cout,
                                            int mt, int nt)
{
    extern __shared__ char sm_raw[];
    const uint32_t smBase = smem_u32(sm_raw);
    const int K = DD, N = DD;

    const int tid  = threadIdx.x;
    const int wid  = tid >> 5;
    const int lane = tid & 31;

    const int row0 = mt * 128;
    const int col0 = nt * 256;

    const int warp_m0 = (wid >> 2) * 64;    // 0 or 64
    const int warp_n0 = (wid & 3) * 64;     // 0,64,128,192
    const int rrow = (lane & 7) + (((lane >> 3) & 1) << 3);
    const int sadd = lane >> 4;

    const __half* Ap = A + (size_t)row0 * K;
    const __half* Wp = W + (size_t)col0 * K;

    const int l_seg = tid & 7;

    auto issue = [&](int c, int st) {
        const uint32_t sa = smBase + st * GM_STAGE;
        const __half* ga = Ap + c * GM_BK + l_seg * 8;
        const __half* gb = Wp + c * GM_BK + l_seg * 8;
#pragma unroll
        for (int it = 0; it < 4; ++it) {
            const int row = (tid + it * 256) >> 3;       // 0..127
            cp16(sa + tile_off(row, l_seg), ga + (size_t)row * K);
        }
#pragma unroll
        for (int it = 0; it < 8; ++it) {
            const int row = (tid + it * 256) >> 3;       // 0..255
            cp16(sa + GM_ATILE + tile_off(row, l_seg), gb + (size_t)row * K);
        }
        CP_COMMIT();
    };

    float acc[4][8][4];
#pragma unroll
    for (int i = 0; i < 4; ++i)
#pragma unroll
        for (int j = 0; j < 8; ++j)
#pragma unroll
            for (int q = 0; q < 4; ++q) acc[i][j][q] = 0.f;

    const int NCH = K / GM_BK;   // 16
    issue(0, 0);
    issue(1, 1);

    for (int c = 0; c < NCH; ++c) {
        const int s = c % 3;
        CP_WAIT(1);
        __syncthreads();
        if (c + 2 < NCH) issue(c + 2, (c + 2) % 3);

        const uint32_t aBase = smBase + s * GM_STAGE;
        const uint32_t bBase = aBase + GM_ATILE;
#pragma unroll
        for (int k = 0; k < 4; ++k) {          // 4 x k16
            const int seg = k * 2 + sadd;
            uint32_t af[4][4], bf[4][4];
#pragma unroll
            for (int i = 0; i < 4; ++i)
                ldmatrix_x4(af[i], aBase + tile_off(warp_m0 + 16 * i + rrow, seg));
#pragma unroll
            for (int j = 0; j < 4; ++j)
                ldmatrix_x4(bf[j], bBase + tile_off(warp_n0 + 16 * j + rrow, seg));
#pragma unroll
            for (int i = 0; i < 4; ++i)
#pragma unroll
                for (int j = 0; j < 4; ++j) {
                    mma_h(acc[i][2 * j],     af[i], bf[j][0], bf[j][2]);
                    mma_h(acc[i][2 * j + 1], af[i], bf[j][1], bf[j][3]);
                }
        }
        __syncthreads();
    }

    // epilogue
    {
        const int g = lane >> 2;
        const int t = lane & 3;
#pragma unroll
        for (int i = 0; i < 4; ++i) {
            const int r = row0 + warp_m0 + 16 * i + g;
#pragma unroll
            for (int jb = 0; jb < 8; ++jb) {
                const int cc = col0 + warp_n0 + 8 * jb + 2 * t;
                const float bx = __ldg(&bias[cc]);
                const float by = __ldg(&bias[cc + 1]);
                const float o0 = acc[i][jb][0] + bx, o1 = acc[i][jb][1] + by;
                const float o2 = acc[i][jb][2] + bx, o3 = acc[i][jb][3] + by;
                if (HALF_OUT) {
                    __half* C = (__half*)Cout;
                    *(uint32_t*)&C[(size_t)r * N + cc]       = h2u(o0, o1);
                    *(uint32_t*)&C[(size_t)(r + 8) * N + cc] = h2u(o2, o3);
                } else {
                    float* C = (float*)Cout;
                    *(float2*)&C[(size_t)r * N + cc]       = make_float2(o0, o1);
                    *(float2*)&C[(size_t)(r + 8) * N + cc] = make_float2(o2, o3);
                }
            }
        }
    }
}

// Fused Q/K/V projections: 1152 CTAs (128 Q + 512 K + 512 V); nt in [0,4)
__global__ __launch_bounds__(256, 1)
void gemm_qkv_kernel(const __half* __restrict__ decH, const __half* __restrict__ encH,
                     const __half* __restrict__ Wq, const __half* __restrict__ Wk,
                     const __half* __restrict__ Wv,
                     const float* __restrict__ bq, const float* __restrict__ bk,
                     const float* __restrict__ bv,
                     __half* __restrict__ Qo, __half* __restrict__ Ko,
                     __half* __restrict__ Vo)
{
    int id = blockIdx.x;
    const __half *A, *W;
    const float* bias;
    __half* C;
    if (id < 128)       { A = decH; W = Wq; bias = bq; C = Qo; }
    else if (id < 640)  { A = encH; W = Wk; bias = bk; C = Ko; id -= 128; }
    else                { A = encH; W = Wv; bias = bv; C = Vo; id -= 640; }
    gemm_core_h<true>(A, W, bias, C, id >> 2, id & 3);
}

__global__ __launch_bounds__(256, 1)
void gemm_o_kernel(const __half* __restrict__ A, const __half* __restrict__ W,
                   const float* __restrict__ bias, float* __restrict__ C)
{
    gemm_core_h<false>(A, W, bias, C, blockIdx.x >> 2, blockIdx.x & 3);
}

// ----------------------------------------------------------------------------
// fp16 tensor-core flash attention (unchanged from R7 — proven).
// CTA: 64 queries x one (b,h); 128 threads (4 warps).
// Smem: Qs 8K | Ks[2] 16K | Vs[2] 16K = 40KB -> 4 CTAs/SM.
// ----------------------------------------------------------------------------
#define FA_SMEM_BYTES (40 * 1024)

__global__ __launch_bounds__(128, 4)
void flash_h_kernel(const __half* __restrict__ Q,
                    const __half* __restrict__ K,
                    const __half* __restrict__ V,
                    __half* __restrict__ O)
{
    extern __shared__ char sm_raw[];
    const uint32_t QsB  = smem_u32(sm_raw);
    const uint32_t KsB0 = QsB + 8192;
    const uint32_t VsB0 = QsB + 24576;

    const int tid  = threadIdx.x;
    const int wid  = tid >> 5;
    const int lane = tid & 31;

    const int y  = blockIdx.y;
    const int b  = y & 3;
    const int h  = c_hmap[y >> 2];
    const int stride = c_stride[h];
    const int t0 = blockIdx.x * 64;

    const int rrow = (lane & 7) + (((lane >> 3) & 1) << 3);
    const int sadd = lane >> 4;
    const int g    = lane >> 2;
    const int t    = lane & 3;
    const int w16  = wid * 16;

    const float C1 = 0.125f * 1.4426950408889634f;  // scale * log2(e)

    const int l_seg = tid & 7;

    const __half* Kb = K + ((size_t)b * SS) * DD + h * HD;
    const __half* Vb = V + ((size_t)b * SS) * DD + h * HD;

    auto kv_issue = [&](int tile, int s) {
        const uint32_t kd = KsB0 + s * 8192;
        const uint32_t vd = VsB0 + s * 8192;
#pragma unroll
        for (int it = 0; it < 4; ++it) {
            const int row = (tid + it * 128) >> 3;
            const int srow = (tile * 64 + row) * stride;
            cp16(kd + tile_off(row, l_seg), Kb + (size_t)srow * DD + l_seg * 8);
        }
#pragma unroll
        for (int it = 0; it < 4; ++it) {
            const int row = (tid + it * 128) >> 3;
            const int srow = (tile * 64 + row) * stride;
            cp16(vd + tile_off(row, l_seg), Vb + (size_t)srow * DD + l_seg * 8);
        }
        CP_COMMIT();
    };

    // prologue: Q + K0 + V0 as one group
    {
        const __half* qb = Q + ((size_t)(b * TT + t0)) * DD + h * HD;
#pragma unroll
        for (int it = 0; it < 4; ++it) {
            const int row = (tid + it * 128) >> 3;
            cp16(QsB + tile_off(row, l_seg), qb + (size_t)row * DD + l_seg * 8);
        }
    }
    kv_issue(0, 0);

    uint32_t qf[4][4];
    float m0 = -INFINITY, m1 = -INFINITY, l0 = 0.f, l1 = 0.f;
    float acc_o[8][4];
#pragma unroll
    for (int jb = 0; jb < 8; ++jb)
#pragma unroll
        for (int q = 0; q < 4; ++q) acc_o[jb][q] = 0.f;

    const int nTiles = SS / (stride * 64);

    for (int tile = 0; tile < nTiles; ++tile) {
        const int s = tile & 1;
        const uint32_t Ks = KsB0 + s * 8192;
        const uint32_t Vs = VsB0 + s * 8192;

        CP_WAIT(0);
        __syncthreads();

        if (tile == 0) {
#pragma unroll
            for (int k = 0; k < 4; ++k)
                ldmatrix_x4(qf[k], QsB + tile_off(w16 + rrow, k * 2 + sadd));
        }
        if (tile + 1 < nTiles) kv_issue(tile + 1, s ^ 1);

        // S = Q @ K^T
        float s_[8][4];
#pragma unroll
        for (int jb = 0; jb < 8; ++jb)
#pragma unroll
            for (int q = 0; q < 4; ++q) s_[jb][q] = 0.f;

#pragma unroll
        for (int k = 0; k < 4; ++k) {
            const int seg = k * 2 + sadd;
#pragma unroll
            for (int j = 0; j < 4; ++j) {
                uint32_t bf[4];
                ldmatrix_x4(bf, Ks + tile_off(16 * j + rrow, seg));
                mma_h(s_[2 * j],     qf[k], bf[0], bf[2]);
                mma_h(s_[2 * j + 1], qf[k], bf[1], bf[3]);
            }
        }
#pragma unroll
        for (int jb = 0; jb < 8; ++jb)
#pragma unroll
            for (int q = 0; q < 4; ++q) s_[jb][q] *= C1;

        // online softmax
        float tm0 = -INFINITY, tm1 = -INFINITY;
#pragma unroll
        for (int jb = 0; jb < 8; ++jb) {
            tm0 = fmaxf(tm0, fmaxf(s_[jb][0], s_[jb][1]));
            tm1 = fmaxf(tm1, fmaxf(s_[jb][2], s_[jb][3]));
        }
#pragma unroll
        for (int msk = 1; msk < 4; msk <<= 1) {
            tm0 = fmaxf(tm0, __shfl_xor_sync(0xffffffffu, tm0, msk));
            tm1 = fmaxf(tm1, __shfl_xor_sync(0xffffffffu, tm1, msk));
        }
        const float mn0 = fmaxf(m0, tm0);
        const float mn1 = fmaxf(m1, tm1);
        const float cr0 = exp2f(m0 - mn0);
        const float cr1 = exp2f(m1 - mn1);
        m0 = mn0; m1 = mn1;

        float sum0 = 0.f, sum1 = 0.f;
#pragma unroll
        for (int jb = 0; jb < 8; ++jb) {
            s_[jb][0] = exp2f(s_[jb][0] - mn0);
            s_[jb][1] = exp2f(s_[jb][1] - mn0);
            s_[jb][2] = exp2f(s_[jb][2] - mn1);
            s_[jb][3] = exp2f(s_[jb][3] - mn1);
            sum0 += s_[jb][0] + s_[jb][1];
            sum1 += s_[jb][2] + s_[jb][3];
        }
#pragma unroll
        for (int msk = 1; msk < 4; msk <<= 1) {
            sum0 += __shfl_xor_sync(0xffffffffu, sum0, msk);
            sum1 += __shfl_xor_sync(0xffffffffu, sum1, msk);
        }
        l0 = l0 * cr0 + sum0;
        l1 = l1 * cr1 + sum1;
#pragma unroll
        for (int jb = 0; jb < 8; ++jb) {
            acc_o[jb][0] *= cr0; acc_o[jb][1] *= cr0;
            acc_o[jb][2] *= cr1; acc_o[jb][3] *= cr1;
        }

        // O += P @ V
#pragma unroll
        for (int kk = 0; kk < 4; ++kk) {
            uint32_t ap[4];
            ap[0] = h2u(s_[2 * kk][0],     s_[2 * kk][1]);
            ap[1] = h2u(s_[2 * kk][2],     s_[2 * kk][3]);
            ap[2] = h2u(s_[2 * kk + 1][0], s_[2 * kk + 1][1]);
            ap[3] = h2u(s_[2 * kk + 1][2], s_[2 * kk + 1][3]);
#pragma unroll
            for (int jj = 0; jj < 4; ++jj) {
                uint32_t bf[4];
                ldmatrix_x4_trans(bf, Vs + tile_off(16 * kk + rrow, 2 * jj + sadd));
                mma_h(acc_o[2 * jj],     ap, bf[0], bf[1]);
                mma_h(acc_o[2 * jj + 1], ap, bf[2], bf[3]);
            }
        }
    }

    // epilogue
    {
        const float inv0 = 1.0f / l0;
        const float inv1 = 1.0f / l1;
        const int r0 = t0 + w16 + g;
        const int r1 = r0 + 8;
#pragma unroll
        for (int jb = 0; jb < 8; ++jb) {
            const int d = jb * 8 + 2 * t;
            *(uint32_t*)&O[((size_t)(b * TT + r0)) * DD + h * HD + d] =
                h2u(acc_o[jb][0] * inv0, acc_o[jb][1] * inv0);
            *(uint32_t*)&O[((size_t)(b * TT + r1)) * DD + h * HD + d] =
                h2u(acc_o[jb][2] * inv1, acc_o[jb][3] * inv1);
        }
    }
}

// ----------------------------------------------------------------------------
// Launch
// ----------------------------------------------------------------------------
extern "C" void kernel_launch(void* const* d_in, const int* in_sizes, int n_in,
                              void* d_out, int out_size)
{
    const float* dec = (const float*)d_in[0];
    const float* enc = (const float*)d_in[1];
    const float* Wq  = (const float*)d_in[2];
    const float* bq  = (const float*)d_in[3];
    const float* Wk  = (const float*)d_in[4];
    const float* bk  = (const float*)d_in[5];
    const float* Wv  = (const float*)d_in[6];
    const float* bv  = (const float*)d_in[7];
    const float* Wo  = (const float*)d_in[8];
    const float* bo  = (const float*)d_in[9];
    float* out = (float*)d_out;

    __half *gQ, *gK, *gV, *gA, *gDec, *gEnc, *gWq, *gWk, *gWv, *gWo;
    cudaGetSymbolAddress((void**)&gQ,   g_Qh);
    cudaGetSymbolAddress((void**)&gK,   g_Kh);
    cudaGetSymbolAddress((void**)&gV,   g_Vh);
    cudaGetSymbolAddress((void**)&gA,   g_attnH);
    cudaGetSymbolAddress((void**)&gDec, g_decH);
    cudaGetSymbolAddress((void**)&gEnc, g_encH);
    cudaGetSymbolAddress((void**)&gWq,  g_WqH);
    cudaGetSymbolAddress((void**)&gWk,  g_WkH);
    cudaGetSymbolAddress((void**)&gWv,  g_WvH);
    cudaGetSymbolAddress((void**)&gWo,  g_WoH);

    cudaFuncSetAttribute(gemm_qkv_kernel,
                         cudaFuncAttributeMaxDynamicSharedMemorySize, GM_SMEM);
    cudaFuncSetAttribute(gemm_o_kernel,
                         cudaFuncAttributeMaxDynamicSharedMemorySize, GM_SMEM);
    cudaFuncSetAttribute(flash_h_kernel,
                         cudaFuncAttributeMaxDynamicSharedMemorySize, FA_SMEM_BYTES);

    // ---- fused convert-to-fp16 prepass (one launch) ----
    {
        const int n4 = N4_ENC + N4_DEC + 4 * N4_W;   // 6M float4
        to_half_all_kernel<<<(n4 + 255) / 256, 256>>>(
            dec, enc, Wq, Wk, Wv, Wo, gDec, gEnc, gWq, gWk, gWv, gWo);
    }

    // ---- fused Q/K/V projections ----
    gemm_qkv_kernel<<<1152, 256, GM_SMEM>>>(gDec, gEnc, gWq, gWk, gWv,
                                            bq, bk, bv, gQ, gK, gV);

    // ---- attention ----
    {
        dim3 grid(TT / 64, BB * HH);
        flash_h_kernel<<<grid, 128, FA_SMEM_BYTES>>>(gQ, gK, gV, gA);
    }

    // ---- output projection ----
    gemm_o_kernel<<<128, 256, GM_SMEM>>>(gA, gWo, bo, out);
}